// round 1
// baseline (speedup 1.0000x reference)
#include <cuda_runtime.h>
#include <cuda_bf16.h>
#include <math.h>

// ---------------- problem constants ----------------
#define BB 64
#define NN 128
#define DLAT 80
#define HEADS 8
#define DH 64
#define INNER 512
#define FFD 160
#define DEPTH 24
#define ROWS (BB * NN)          // 8192
#define MHD 20

// ---------------- scratch (device globals; no allocation allowed) ----------
__device__ float g_bias[BB * NN * NN];          // 4 MB
__device__ float g_x[ROWS * DLAT];
__device__ float g_h[ROWS * DLAT];
__device__ float g_q[ROWS * INNER];
__device__ float g_kv[ROWS * 2 * INNER];
__device__ float g_o[ROWS * INNER];
__device__ float g_ff[ROWS * FFD];

// ---------------- bias precompute ----------------
__global__ __launch_bounds__(256) void bias_kernel(
    const int* __restrict__ sp, const int* __restrict__ ei,
    const float* __restrict__ eemb, const float* __restrict__ edw,
    const float* __restrict__ semb, float* __restrict__ bias)
{
    __shared__ float s_eemb[64];
    __shared__ float s_edw[MHD];
    __shared__ float s_semb[40];
    int tid = threadIdx.x;
    if (tid < 64) s_eemb[tid] = eemb[tid];
    if (tid < MHD) s_edw[tid] = edw[tid];
    if (tid < 40) s_semb[tid] = semb[tid];
    __syncthreads();
    int g = blockIdx.x * blockDim.x + tid;
    if (g >= BB * NN * NN) return;
    const int* ep = ei + (size_t)g * (MHD * 3);
    float acc = 0.f;
#pragma unroll
    for (int hh = 0; hh < MHD; ++hh) {
        float m = (s_eemb[ep[hh * 3]] + s_eemb[ep[hh * 3 + 1]] + s_eemb[ep[hh * 3 + 2]]) * (1.f / 3.f);
        acc += m * s_edw[hh];
    }
    int p = sp[g];
    int spv = (p == 0) ? 1 : p;
    if (spv > 1) spv -= 1;
    if (spv > MHD) spv = MHD;
    bias[g] = acc / (float)spv + s_semb[p];
}

// ---------------- node embedding ----------------
__global__ __launch_bounds__(256) void embed_kernel(
    const int* __restrict__ xn, const int* __restrict__ ind, const int* __restrict__ outd,
    const float* __restrict__ ae, const float* __restrict__ ie, const float* __restrict__ oe,
    float* __restrict__ x)
{
    int i = blockIdx.x * blockDim.x + threadIdx.x;
    if (i >= ROWS * DLAT) return;
    int row = i / DLAT, d = i - row * DLAT;
    x[i] = ae[xn[row] * DLAT + d] + ie[ind[row] * DLAT + d] + oe[outd[row] * DLAT + d];
}

// ---------------- LayerNorm (warp per row, D=80) ----------------
__global__ __launch_bounds__(256) void ln_kernel(
    const float* __restrict__ x, const float* __restrict__ g,
    const float* __restrict__ bt, float* __restrict__ y)
{
    int gw = (blockIdx.x * blockDim.x + threadIdx.x) >> 5;
    int lane = threadIdx.x & 31;
    if (gw >= ROWS) return;
    const float* xr = x + (size_t)gw * DLAT;
    float v0 = xr[lane];
    float v1 = xr[lane + 32];
    float v2 = (lane < 16) ? xr[lane + 64] : 0.f;
    float s = v0 + v1 + v2;
#pragma unroll
    for (int off = 16; off > 0; off >>= 1) s += __shfl_xor_sync(0xffffffffu, s, off);
    float mean = s * (1.f / 80.f);
    float d0 = v0 - mean, d1 = v1 - mean, d2 = (lane < 16) ? (v2 - mean) : 0.f;
    float sq = d0 * d0 + d1 * d1 + d2 * d2;
#pragma unroll
    for (int off = 16; off > 0; off >>= 1) sq += __shfl_xor_sync(0xffffffffu, sq, off);
    float rstd = rsqrtf(sq * (1.f / 80.f) + 1e-5f);
    float* yr = y + (size_t)gw * DLAT;
    yr[lane] = d0 * rstd * g[lane] + bt[lane];
    yr[lane + 32] = d1 * rstd * g[lane + 32] + bt[lane + 32];
    if (lane < 16) yr[lane + 64] = d2 * rstd * g[lane + 64] + bt[lane + 64];
}

// ---------------- generic 64x64 tiled SGEMM with fused epilogues -----------
// flags: 1 = add bias (per col), 2 = exact GELU, 4 = add residual (same shape as C)
__global__ __launch_bounds__(256) void gemm64_kernel(
    const float* __restrict__ A, const float* __restrict__ W,
    const float* __restrict__ bi, const float* __restrict__ res,
    float* __restrict__ C, int M, int N, int K, int flags)
{
    __shared__ float As[16][64];
    __shared__ float Bs[16][68];
    int tid = threadIdx.x;
    int tx = tid & 15, ty = tid >> 4;
    int m0 = blockIdx.y * 64, n0 = blockIdx.x * 64;
    float acc[4][4] = {};
    int ar = tid >> 2, ak = (tid & 3) * 4;
    int bk = tid >> 4, bn = (tid & 15) * 4;
    for (int k0 = 0; k0 < K; k0 += 16) {
        float4 a4 = *(const float4*)(A + (size_t)(m0 + ar) * K + k0 + ak);
        As[ak + 0][ar] = a4.x; As[ak + 1][ar] = a4.y;
        As[ak + 2][ar] = a4.z; As[ak + 3][ar] = a4.w;
        int gc = n0 + bn;
        const float* wrow = W + (size_t)(k0 + bk) * N;
        float4 b4;
        if (gc + 3 < N) {
            b4 = *(const float4*)(wrow + gc);
        } else {
            b4.x = (gc + 0 < N) ? wrow[gc + 0] : 0.f;
            b4.y = (gc + 1 < N) ? wrow[gc + 1] : 0.f;
            b4.z = (gc + 2 < N) ? wrow[gc + 2] : 0.f;
            b4.w = (gc + 3 < N) ? wrow[gc + 3] : 0.f;
        }
        *(float4*)&Bs[bk][bn] = b4;
        __syncthreads();
#pragma unroll
        for (int kk = 0; kk < 16; ++kk) {
            float4 av = *(const float4*)&As[kk][ty * 4];
            float4 bv = *(const float4*)&Bs[kk][tx * 4];
            float aa[4] = {av.x, av.y, av.z, av.w};
            float bb2[4] = {bv.x, bv.y, bv.z, bv.w};
#pragma unroll
            for (int i = 0; i < 4; ++i)
#pragma unroll
                for (int j = 0; j < 4; ++j)
                    acc[i][j] += aa[i] * bb2[j];
        }
        __syncthreads();
    }
#pragma unroll
    for (int i = 0; i < 4; ++i) {
        int row = m0 + ty * 4 + i;
#pragma unroll
        for (int j = 0; j < 4; ++j) {
            int col = n0 + tx * 4 + j;
            if (col < N) {
                float v = acc[i][j];
                if (flags & 1) v += bi[col];
                if (flags & 2) v = 0.5f * v * (1.0f + erff(v * 0.70710678118f));
                if (flags & 4) v += res[(size_t)row * N + col];
                C[(size_t)row * N + col] = v;
            }
        }
    }
}

// ---------------- fused attention per (b, head) ----------------
// smem: Qs[128][64] | Kt[64][129] | Vs[128][64] | Sb[8][4][128]
#define ATTN_SMEM ((128 * 64 + 64 * 129 + 128 * 64 + 8 * 512) * 4)
__global__ __launch_bounds__(256) void attn_kernel(
    const float* __restrict__ q, const float* __restrict__ kv,
    const float* __restrict__ bias, float* __restrict__ o)
{
    extern __shared__ float sm[];
    float* Qs = sm;                       // 8192
    float* Kt = sm + 128 * 64;            // 64*129 = 8256
    float* Vs = Kt + 64 * 129;            // 8192
    float* Sb = Vs + 128 * 64;            // 8*512
    int bh = blockIdx.x;
    int b = bh >> 3, hh = bh & 7;
    const float* qp = q + (size_t)b * NN * INNER + hh * DH;
    const float* kp = kv + (size_t)b * NN * (2 * INNER) + hh * DH;
    const float* vp = kp + INNER;
    int tid = threadIdx.x;
    for (int idx = tid; idx < 128 * 64; idx += 256) {
        int r = idx >> 6, c = idx & 63;
        Qs[r * 64 + c] = qp[(size_t)r * INNER + c];
        Kt[c * 129 + r] = kp[(size_t)r * (2 * INNER) + c];
        Vs[r * 64 + c] = vp[(size_t)r * (2 * INNER) + c];
    }
    __syncthreads();
    int w = tid >> 5, lane = tid & 31;
    float* Sw = Sb + w * 512;
    const float* bb = bias + (size_t)b * NN * NN;
    float* op = o + (size_t)b * NN * INNER + hh * DH;

    for (int ib = 0; ib < 4; ++ib) {
        int i0 = w * 16 + ib * 4;
        float acc[4][4] = {};
        for (int k4 = 0; k4 < 64; k4 += 4) {
            float qa[4][4];
#pragma unroll
            for (int ii = 0; ii < 4; ++ii) {
                float4 t = *(const float4*)&Qs[(i0 + ii) * 64 + k4];
                qa[ii][0] = t.x; qa[ii][1] = t.y; qa[ii][2] = t.z; qa[ii][3] = t.w;
            }
#pragma unroll
            for (int t = 0; t < 4; ++t) {
                float kr[4];
#pragma unroll
                for (int jj = 0; jj < 4; ++jj) kr[jj] = Kt[(k4 + t) * 129 + lane + jj * 32];
#pragma unroll
                for (int ii = 0; ii < 4; ++ii)
#pragma unroll
                    for (int jj = 0; jj < 4; ++jj)
                        acc[ii][jj] += qa[ii][t] * kr[jj];
            }
        }
        float rsum[4];
#pragma unroll
        for (int ii = 0; ii < 4; ++ii) {
            float s[4];
#pragma unroll
            for (int jj = 0; jj < 4; ++jj)
                s[jj] = acc[ii][jj] * 0.125f + __ldg(&bb[(size_t)(i0 + ii) * NN + lane + jj * 32]);
            float m = fmaxf(fmaxf(s[0], s[1]), fmaxf(s[2], s[3]));
#pragma unroll
            for (int off = 16; off > 0; off >>= 1) m = fmaxf(m, __shfl_xor_sync(0xffffffffu, m, off));
            float e[4], sum = 0.f;
#pragma unroll
            for (int jj = 0; jj < 4; ++jj) { e[jj] = __expf(s[jj] - m); sum += e[jj]; }
#pragma unroll
            for (int off = 16; off > 0; off >>= 1) sum += __shfl_xor_sync(0xffffffffu, sum, off);
            rsum[ii] = sum;
#pragma unroll
            for (int jj = 0; jj < 4; ++jj) Sw[ii * 128 + lane + jj * 32] = e[jj];
        }
        __syncwarp();
        float oa[4][2] = {};
        for (int j4 = 0; j4 < 128; j4 += 4) {
            float pa[4][4];
#pragma unroll
            for (int ii = 0; ii < 4; ++ii) {
                float4 t = *(const float4*)&Sw[ii * 128 + j4];
                pa[ii][0] = t.x; pa[ii][1] = t.y; pa[ii][2] = t.z; pa[ii][3] = t.w;
            }
#pragma unroll
            for (int t = 0; t < 4; ++t) {
                float2 v2 = *(const float2*)&Vs[(j4 + t) * 64 + 2 * lane];
#pragma unroll
                for (int ii = 0; ii < 4; ++ii) {
                    oa[ii][0] += pa[ii][t] * v2.x;
                    oa[ii][1] += pa[ii][t] * v2.y;
                }
            }
        }
#pragma unroll
        for (int ii = 0; ii < 4; ++ii) {
            float inv = 1.f / rsum[ii];
            float2 r2;
            r2.x = oa[ii][0] * inv;
            r2.y = oa[ii][1] * inv;
            *(float2*)&op[(size_t)(i0 + ii) * INNER + 2 * lane] = r2;
        }
        __syncwarp();
    }
}

// ---------------- final head: mean-pool over N, LN, Linear(80->1) ----------
__global__ __launch_bounds__(128) void head_kernel(
    const float* __restrict__ x, const float* __restrict__ g, const float* __restrict__ bt,
    const float* __restrict__ wf, const float* __restrict__ bf, float* __restrict__ out)
{
    int b = blockIdx.x;
    __shared__ float pooled[DLAT];
    int tid = threadIdx.x;
    if (tid < DLAT) {
        float s = 0.f;
        for (int n = 0; n < NN; ++n) s += x[((size_t)b * NN + n) * DLAT + tid];
        pooled[tid] = s * (1.f / 128.f);
    }
    __syncthreads();
    if (tid == 0) {
        float m = 0.f;
        for (int d = 0; d < DLAT; ++d) m += pooled[d];
        m *= (1.f / 80.f);
        float v = 0.f;
        for (int d = 0; d < DLAT; ++d) { float t = pooled[d] - m; v += t * t; }
        v *= (1.f / 80.f);
        float rstd = rsqrtf(v + 1e-5f);
        float r = 0.f;
        for (int d = 0; d < DLAT; ++d)
            r += ((pooled[d] - m) * rstd * g[d] + bt[d]) * wf[d];
        out[b] = r + bf[0];
    }
}

// ---------------- launcher ----------------
extern "C" void kernel_launch(void* const* d_in, const int* in_sizes, int n_in,
                              void* d_out, int out_size)
{
    const int*   spatial_pos = (const int*)d_in[0];
    const int*   edge_input  = (const int*)d_in[1];
    const int*   x_nodes     = (const int*)d_in[2];
    const int*   indeg       = (const int*)d_in[3];
    const int*   outdeg      = (const int*)d_in[4];
    const float* atom_emb    = (const float*)d_in[5];
    const float* indeg_emb   = (const float*)d_in[6];
    const float* outdeg_emb  = (const float*)d_in[7];
    const float* edge_emb    = (const float*)d_in[8];
    const float* edge_dis_w  = (const float*)d_in[9];
    const float* spatial_emb = (const float*)d_in[10];
    const float* ln1_g = (const float*)d_in[11];
    const float* ln1_b = (const float*)d_in[12];
    const float* Wq    = (const float*)d_in[13];
    const float* Wkv   = (const float*)d_in[14];
    const float* Wo    = (const float*)d_in[15];
    const float* bo    = (const float*)d_in[16];
    const float* ln2_g = (const float*)d_in[17];
    const float* ln2_b = (const float*)d_in[18];
    const float* W1    = (const float*)d_in[19];
    const float* b1    = (const float*)d_in[20];
    const float* W2    = (const float*)d_in[21];
    const float* b2    = (const float*)d_in[22];
    const float* lnf_g = (const float*)d_in[23];
    const float* lnf_b = (const float*)d_in[24];
    const float* Wf    = (const float*)d_in[25];
    const float* bf    = (const float*)d_in[26];
    float* out = (float*)d_out;

    float *bias_p, *x_p, *h_p, *q_p, *kv_p, *o_p, *ff_p;
    cudaGetSymbolAddress((void**)&bias_p, g_bias);
    cudaGetSymbolAddress((void**)&x_p, g_x);
    cudaGetSymbolAddress((void**)&h_p, g_h);
    cudaGetSymbolAddress((void**)&q_p, g_q);
    cudaGetSymbolAddress((void**)&kv_p, g_kv);
    cudaGetSymbolAddress((void**)&o_p, g_o);
    cudaGetSymbolAddress((void**)&ff_p, g_ff);

    cudaFuncSetAttribute(attn_kernel, cudaFuncAttributeMaxDynamicSharedMemorySize, ATTN_SMEM);

    bias_kernel<<<(BB * NN * NN) / 256, 256>>>(spatial_pos, edge_input, edge_emb, edge_dis_w,
                                               spatial_emb, bias_p);
    embed_kernel<<<(ROWS * DLAT + 255) / 256, 256>>>(x_nodes, indeg, outdeg,
                                                     atom_emb, indeg_emb, outdeg_emb, x_p);
    for (int l = 0; l < DEPTH; ++l) {
        ln_kernel<<<ROWS / 8, 256>>>(x_p, ln1_g + l * DLAT, ln1_b + l * DLAT, h_p);
        gemm64_kernel<<<dim3(INNER / 64, ROWS / 64), 256>>>(
            h_p, Wq + (size_t)l * DLAT * INNER, nullptr, nullptr, q_p, ROWS, INNER, DLAT, 0);
        gemm64_kernel<<<dim3(2 * INNER / 64, ROWS / 64), 256>>>(
            h_p, Wkv + (size_t)l * DLAT * 2 * INNER, nullptr, nullptr, kv_p, ROWS, 2 * INNER, DLAT, 0);
        attn_kernel<<<BB * HEADS, 256, ATTN_SMEM>>>(q_p, kv_p, bias_p, o_p);
        gemm64_kernel<<<dim3(2, ROWS / 64), 256>>>(
            o_p, Wo + (size_t)l * INNER * DLAT, bo + l * DLAT, x_p, x_p, ROWS, DLAT, INNER, 5);
        ln_kernel<<<ROWS / 8, 256>>>(x_p, ln2_g + l * DLAT, ln2_b + l * DLAT, h_p);
        gemm64_kernel<<<dim3(3, ROWS / 64), 256>>>(
            h_p, W1 + (size_t)l * DLAT * FFD, b1 + l * FFD, nullptr, ff_p, ROWS, FFD, DLAT, 3);
        gemm64_kernel<<<dim3(2, ROWS / 64), 256>>>(
            ff_p, W2 + (size_t)l * FFD * DLAT, b2 + l * DLAT, x_p, x_p, ROWS, DLAT, FFD, 5);
    }
    head_kernel<<<BB, 128>>>(x_p, lnf_g, lnf_b, Wf, bf, out);
}

// round 4
// speedup vs baseline: 1.6888x; 1.6888x over previous
#include <cuda_runtime.h>
#include <cuda_bf16.h>
#include <math.h>
#include <stdint.h>

// ---------------- problem constants ----------------
#define BB 64
#define NN 128
#define DLAT 80
#define HEADS 8
#define DH 64
#define INNER 512
#define FFD 160
#define DEPTH 24
#define ROWS (BB * NN)          // 8192
#define MHD 20

// ---------------- scratch (device globals; no allocation allowed) ----------
__device__ float g_bias[BB * NN * NN];          // 4 MB
__device__ float g_x[ROWS * DLAT];
__device__ float g_h[ROWS * DLAT];
__device__ float g_q[ROWS * INNER];
__device__ float g_kv[ROWS * 2 * INNER];
__device__ float g_o[ROWS * INNER];
__device__ float g_ff[ROWS * FFD];

// ---------------- tf32 helpers ----------------
__device__ __forceinline__ uint32_t f2tf(float x) {
    uint32_t r;
    asm("cvt.rna.tf32.f32 %0, %1;" : "=r"(r) : "f"(x));
    return r;
}

__device__ __forceinline__ void mma_tf32(float* c, const uint32_t* a, uint32_t b0, uint32_t b1) {
    asm("mma.sync.aligned.m16n8k8.row.col.f32.tf32.tf32.f32 "
        "{%0,%1,%2,%3},{%4,%5,%6,%7},{%8,%9},{%0,%1,%2,%3};"
        : "+f"(c[0]), "+f"(c[1]), "+f"(c[2]), "+f"(c[3])
        : "r"(a[0]), "r"(a[1]), "r"(a[2]), "r"(a[3]), "r"(b0), "r"(b1));
}

// ---------------- bias precompute ----------------
__global__ __launch_bounds__(256) void bias_kernel(
    const int* __restrict__ sp, const int* __restrict__ ei,
    const float* __restrict__ eemb, const float* __restrict__ edw,
    const float* __restrict__ semb, float* __restrict__ bias)
{
    __shared__ float s_eemb[64];
    __shared__ float s_edw[MHD];
    __shared__ float s_semb[40];
    int tid = threadIdx.x;
    if (tid < 64) s_eemb[tid] = eemb[tid];
    if (tid < MHD) s_edw[tid] = edw[tid];
    if (tid < 40) s_semb[tid] = semb[tid];
    __syncthreads();
    int g = blockIdx.x * blockDim.x + tid;
    if (g >= BB * NN * NN) return;
    const int* ep = ei + (size_t)g * (MHD * 3);
    float acc = 0.f;
#pragma unroll
    for (int hh = 0; hh < MHD; ++hh) {
        float m = (s_eemb[ep[hh * 3]] + s_eemb[ep[hh * 3 + 1]] + s_eemb[ep[hh * 3 + 2]]) * (1.f / 3.f);
        acc += m * s_edw[hh];
    }
    int p = sp[g];
    int spv = (p == 0) ? 1 : p;
    if (spv > 1) spv -= 1;
    if (spv > MHD) spv = MHD;
    bias[g] = acc / (float)spv + s_semb[p];
}

// ---------------- node embedding ----------------
__global__ __launch_bounds__(256) void embed_kernel(
    const int* __restrict__ xn, const int* __restrict__ ind, const int* __restrict__ outd,
    const float* __restrict__ ae, const float* __restrict__ ie, const float* __restrict__ oe,
    float* __restrict__ x)
{
    int i = blockIdx.x * blockDim.x + threadIdx.x;
    if (i >= ROWS * DLAT) return;
    int row = i / DLAT, d = i - row * DLAT;
    x[i] = ae[xn[row] * DLAT + d] + ie[ind[row] * DLAT + d] + oe[outd[row] * DLAT + d];
}

// ---------------- LayerNorm (warp per row, D=80) ----------------
__global__ __launch_bounds__(256) void ln_kernel(
    const float* __restrict__ x, const float* __restrict__ g,
    const float* __restrict__ bt, float* __restrict__ y)
{
    int gw = (blockIdx.x * blockDim.x + threadIdx.x) >> 5;
    int lane = threadIdx.x & 31;
    if (gw >= ROWS) return;
    const float* xr = x + (size_t)gw * DLAT;
    float v0 = xr[lane];
    float v1 = xr[lane + 32];
    float v2 = (lane < 16) ? xr[lane + 64] : 0.f;
    float s = v0 + v1 + v2;
#pragma unroll
    for (int off = 16; off > 0; off >>= 1) s += __shfl_xor_sync(0xffffffffu, s, off);
    float mean = s * (1.f / 80.f);
    float d0 = v0 - mean, d1 = v1 - mean, d2 = (lane < 16) ? (v2 - mean) : 0.f;
    float sq = d0 * d0 + d1 * d1 + d2 * d2;
#pragma unroll
    for (int off = 16; off > 0; off >>= 1) sq += __shfl_xor_sync(0xffffffffu, sq, off);
    float rstd = rsqrtf(sq * (1.f / 80.f) + 1e-5f);
    float* yr = y + (size_t)gw * DLAT;
    yr[lane] = d0 * rstd * g[lane] + bt[lane];
    yr[lane + 32] = d1 * rstd * g[lane + 32] + bt[lane + 32];
    if (lane < 16) yr[lane + 64] = d2 * rstd * g[lane + 64] + bt[lane + 64];
}

// ---------------- tf32 tensor-core GEMM ----------------
// C[M,N] = A[M,K] @ W[K,N], exact tiling (M % BM == 0, N % BN == 0).
// flags: 1 = +bias(col), 2 = exact GELU, 4 = +residual
template<int BM, int BN>
__global__ __launch_bounds__(256) void gemm_mma_kernel(
    const float* __restrict__ A, const float* __restrict__ W,
    const float* __restrict__ bi, const float* __restrict__ res,
    float* __restrict__ C, int M, int N, int K, int flags)
{
    constexpr int BK = 32;
    constexpr int MI = BM / 64;       // m16 tiles per warp
    constexpr int NI = BN / 16;       // n8 tiles per warp
    constexpr int AP = BK + 4;        // A smem pitch
    constexpr int BP = BN + 8;        // B smem pitch (conflict-free)
    __shared__ uint32_t As[BM * AP];
    __shared__ uint32_t Bs[BK * BP];
    int tid = threadIdx.x;
    int wid = tid >> 5, lane = tid & 31;
    int warpM = wid >> 1, warpN = wid & 1;
    int m0 = blockIdx.y * BM, n0 = blockIdx.x * BN;
    int lq = lane >> 2, lr = lane & 3;

    float c[MI][NI][4];
#pragma unroll
    for (int mi = 0; mi < MI; ++mi)
#pragma unroll
        for (int ni = 0; ni < NI; ++ni)
#pragma unroll
            for (int t = 0; t < 4; ++t) c[mi][ni][t] = 0.f;

    for (int k0 = 0; k0 < K; k0 += BK) {
        __syncthreads();
        // A tile: BM x 32
#pragma unroll
        for (int idx = tid; idx < BM * 8; idx += 256) {
            int r = idx >> 3, c4 = idx & 7;
            int gk = k0 + c4 * 4;
            float4 v = make_float4(0.f, 0.f, 0.f, 0.f);
            if (gk < K) v = *(const float4*)(A + (size_t)(m0 + r) * K + gk);
            uint32_t* d = &As[r * AP + c4 * 4];
            d[0] = f2tf(v.x); d[1] = f2tf(v.y); d[2] = f2tf(v.z); d[3] = f2tf(v.w);
        }
        // B tile: 32 x BN
        for (int idx = tid; idx < BK * (BN / 4); idx += 256) {
            int r = idx / (BN / 4), c4 = idx % (BN / 4);
            int gk = k0 + r;
            float4 v = make_float4(0.f, 0.f, 0.f, 0.f);
            if (gk < K) v = *(const float4*)(W + (size_t)gk * N + n0 + c4 * 4);
            uint32_t* d = &Bs[r * BP + c4 * 4];
            d[0] = f2tf(v.x); d[1] = f2tf(v.y); d[2] = f2tf(v.z); d[3] = f2tf(v.w);
        }
        __syncthreads();
#pragma unroll
        for (int kk = 0; kk < BK; kk += 8) {
            uint32_t a[MI][4];
#pragma unroll
            for (int mi = 0; mi < MI; ++mi) {
                int row = warpM * (16 * MI) + mi * 16 + lq;
                a[mi][0] = As[row * AP + kk + lr];
                a[mi][1] = As[(row + 8) * AP + kk + lr];
                a[mi][2] = As[row * AP + kk + lr + 4];
                a[mi][3] = As[(row + 8) * AP + kk + lr + 4];
            }
#pragma unroll
            for (int ni = 0; ni < NI; ++ni) {
                int col = warpN * (8 * NI) + ni * 8 + lq;
                uint32_t b0 = Bs[(kk + lr) * BP + col];
                uint32_t b1 = Bs[(kk + lr + 4) * BP + col];
#pragma unroll
                for (int mi = 0; mi < MI; ++mi) mma_tf32(c[mi][ni], a[mi], b0, b1);
            }
        }
    }
    // epilogue
#pragma unroll
    for (int mi = 0; mi < MI; ++mi) {
        int r = m0 + warpM * (16 * MI) + mi * 16 + lq;
#pragma unroll
        for (int ni = 0; ni < NI; ++ni) {
            int cc = n0 + warpN * (8 * NI) + ni * 8 + 2 * lr;
#pragma unroll
            for (int half = 0; half < 2; ++half) {
                int row = r + half * 8;
                float v0 = c[mi][ni][half * 2 + 0];
                float v1 = c[mi][ni][half * 2 + 1];
                if (flags & 1) { v0 += bi[cc]; v1 += bi[cc + 1]; }
                if (flags & 2) {
                    v0 = 0.5f * v0 * (1.0f + erff(v0 * 0.70710678118f));
                    v1 = 0.5f * v1 * (1.0f + erff(v1 * 0.70710678118f));
                }
                if (flags & 4) {
                    float2 rv = *(const float2*)(res + (size_t)row * N + cc);
                    v0 += rv.x; v1 += rv.y;
                }
                float2 ov; ov.x = v0; ov.y = v1;
                *(float2*)(C + (size_t)row * N + cc) = ov;
            }
        }
    }
}

// ---------------- fused tensor-core attention per (b, head) ----------------
// smem (uint32 words): Ks[128*68] | Vs[128*68] | QP = union(Qs[128*68], P[8*16*132])
#define AT_KPITCH 68
#define AT_PPITCH 132
#define AT_SMEM_WORDS (128 * AT_KPITCH * 2 + 8 * 16 * AT_PPITCH)
#define AT_SMEM_BYTES (AT_SMEM_WORDS * 4)
__global__ __launch_bounds__(256) void attn_mma_kernel(
    const float* __restrict__ q, const float* __restrict__ kv,
    const float* __restrict__ bias, float* __restrict__ o)
{
    extern __shared__ uint32_t sm[];
    uint32_t* Ks = sm;
    uint32_t* Vs = sm + 128 * AT_KPITCH;
    uint32_t* QP = sm + 2 * 128 * AT_KPITCH;

    int bh = blockIdx.x;
    int b = bh >> 3, hh = bh & 7;
    const float* qp = q + (size_t)b * NN * INNER + hh * DH;
    const float* kp = kv + (size_t)b * NN * (2 * INNER) + hh * DH;
    const float* vp = kp + INNER;
    int tid = threadIdx.x;

    // load Q, K, V tiles (tf32-converted)
#pragma unroll
    for (int idx = tid; idx < 128 * 16; idx += 256) {
        int r = idx >> 4, c4 = (idx & 15) * 4;
        float4 qv = *(const float4*)(qp + (size_t)r * INNER + c4);
        float4 kvv = *(const float4*)(kp + (size_t)r * (2 * INNER) + c4);
        float4 vv = *(const float4*)(vp + (size_t)r * (2 * INNER) + c4);
        uint32_t* dq = &QP[r * AT_KPITCH + c4];
        uint32_t* dk = &Ks[r * AT_KPITCH + c4];
        uint32_t* dv = &Vs[r * AT_KPITCH + c4];
        dq[0] = f2tf(qv.x); dq[1] = f2tf(qv.y); dq[2] = f2tf(qv.z); dq[3] = f2tf(qv.w);
        dk[0] = f2tf(kvv.x); dk[1] = f2tf(kvv.y); dk[2] = f2tf(kvv.z); dk[3] = f2tf(kvv.w);
        dv[0] = f2tf(vv.x); dv[1] = f2tf(vv.y); dv[2] = f2tf(vv.z); dv[3] = f2tf(vv.w);
    }
    __syncthreads();

    int w = tid >> 5, lane = tid & 31;
    int lq = lane >> 2, lr = lane & 3;
    int i0 = w * 16;

    // phase 1: S = Q K^T  (warp: rows i0..i0+15 x all 128 cols)
    float s[16][4];
#pragma unroll
    for (int ni = 0; ni < 16; ++ni)
#pragma unroll
        for (int t = 0; t < 4; ++t) s[ni][t] = 0.f;

#pragma unroll
    for (int kt = 0; kt < 8; ++kt) {
        uint32_t a[4];
        int row = i0 + lq;
        a[0] = QP[row * AT_KPITCH + kt * 8 + lr];
        a[1] = QP[(row + 8) * AT_KPITCH + kt * 8 + lr];
        a[2] = QP[row * AT_KPITCH + kt * 8 + lr + 4];
        a[3] = QP[(row + 8) * AT_KPITCH + kt * 8 + lr + 4];
#pragma unroll
        for (int ni = 0; ni < 16; ++ni) {
            uint32_t b0 = Ks[(ni * 8 + lq) * AT_KPITCH + kt * 8 + lr];
            uint32_t b1 = Ks[(ni * 8 + lq) * AT_KPITCH + kt * 8 + lr + 4];
            mma_tf32(s[ni], a, b0, b1);
        }
    }

    // scale + bias + softmax (rows r0 = i0+lq, r1 = r0+8)
    const float* bb = bias + (size_t)b * NN * NN;
    int r0 = i0 + lq;
#pragma unroll
    for (int ni = 0; ni < 16; ++ni) {
        int cc = ni * 8 + 2 * lr;
        float2 b0v = __ldg((const float2*)(bb + (size_t)r0 * NN + cc));
        float2 b1v = __ldg((const float2*)(bb + (size_t)(r0 + 8) * NN + cc));
        s[ni][0] = s[ni][0] * 0.125f + b0v.x;
        s[ni][1] = s[ni][1] * 0.125f + b0v.y;
        s[ni][2] = s[ni][2] * 0.125f + b1v.x;
        s[ni][3] = s[ni][3] * 0.125f + b1v.y;
    }
    float mA = -1e30f, mB = -1e30f;
#pragma unroll
    for (int ni = 0; ni < 16; ++ni) {
        mA = fmaxf(mA, fmaxf(s[ni][0], s[ni][1]));
        mB = fmaxf(mB, fmaxf(s[ni][2], s[ni][3]));
    }
    mA = fmaxf(mA, __shfl_xor_sync(0xffffffffu, mA, 1));
    mA = fmaxf(mA, __shfl_xor_sync(0xffffffffu, mA, 2));
    mB = fmaxf(mB, __shfl_xor_sync(0xffffffffu, mB, 1));
    mB = fmaxf(mB, __shfl_xor_sync(0xffffffffu, mB, 2));
    float sA = 0.f, sB = 0.f;
#pragma unroll
    for (int ni = 0; ni < 16; ++ni) {
        s[ni][0] = __expf(s[ni][0] - mA);
        s[ni][1] = __expf(s[ni][1] - mA);
        s[ni][2] = __expf(s[ni][2] - mB);
        s[ni][3] = __expf(s[ni][3] - mB);
        sA += s[ni][0] + s[ni][1];
        sB += s[ni][2] + s[ni][3];
    }
    sA += __shfl_xor_sync(0xffffffffu, sA, 1);
    sA += __shfl_xor_sync(0xffffffffu, sA, 2);
    sB += __shfl_xor_sync(0xffffffffu, sB, 1);
    sB += __shfl_xor_sync(0xffffffffu, sB, 2);

    // all warps must be done reading Q before P overwrites the union region
    __syncthreads();
    uint32_t* Pw = QP + w * 16 * AT_PPITCH;
#pragma unroll
    for (int ni = 0; ni < 16; ++ni) {
        int cc = ni * 8 + 2 * lr;
        Pw[lq * AT_PPITCH + cc] = f2tf(s[ni][0]);
        Pw[lq * AT_PPITCH + cc + 1] = f2tf(s[ni][1]);
        Pw[(lq + 8) * AT_PPITCH + cc] = f2tf(s[ni][2]);
        Pw[(lq + 8) * AT_PPITCH + cc + 1] = f2tf(s[ni][3]);
    }
    __syncwarp();

    // phase 2: O = P V  (warp: m16 x n64, k = 128)
    float oc[8][4];
#pragma unroll
    for (int ni = 0; ni < 8; ++ni)
#pragma unroll
        for (int t = 0; t < 4; ++t) oc[ni][t] = 0.f;
#pragma unroll
    for (int kt = 0; kt < 16; ++kt) {
        uint32_t a[4];
        a[0] = Pw[lq * AT_PPITCH + kt * 8 + lr];
        a[1] = Pw[(lq + 8) * AT_PPITCH + kt * 8 + lr];
        a[2] = Pw[lq * AT_PPITCH + kt * 8 + lr + 4];
        a[3] = Pw[(lq + 8) * AT_PPITCH + kt * 8 + lr + 4];
#pragma unroll
        for (int ni = 0; ni < 8; ++ni) {
            uint32_t b0 = Vs[(kt * 8 + lr) * AT_KPITCH + ni * 8 + lq];
            uint32_t b1 = Vs[(kt * 8 + lr + 4) * AT_KPITCH + ni * 8 + lq];
            mma_tf32(oc[ni], a, b0, b1);
        }
    }
    // normalize + store
    float invA = 1.f / sA, invB = 1.f / sB;
    float* op = o + (size_t)b * NN * INNER + hh * DH;
#pragma unroll
    for (int ni = 0; ni < 8; ++ni) {
        int cc = ni * 8 + 2 * lr;
        float2 v0; v0.x = oc[ni][0] * invA; v0.y = oc[ni][1] * invA;
        float2 v1; v1.x = oc[ni][2] * invB; v1.y = oc[ni][3] * invB;
        *(float2*)(op + (size_t)r0 * INNER + cc) = v0;
        *(float2*)(op + (size_t)(r0 + 8) * INNER + cc) = v1;
    }
}

// ---------------- final head: mean-pool over N, LN, Linear(80->1) ----------
__global__ __launch_bounds__(128) void head_kernel(
    const float* __restrict__ x, const float* __restrict__ g, const float* __restrict__ bt,
    const float* __restrict__ wf, const float* __restrict__ bf, float* __restrict__ out)
{
    int b = blockIdx.x;
    __shared__ float pooled[DLAT];
    int tid = threadIdx.x;
    if (tid < DLAT) {
        float s = 0.f;
        for (int n = 0; n < NN; ++n) s += x[((size_t)b * NN + n) * DLAT + tid];
        pooled[tid] = s * (1.f / 128.f);
    }
    __syncthreads();
    if (tid == 0) {
        float m = 0.f;
        for (int d = 0; d < DLAT; ++d) m += pooled[d];
        m *= (1.f / 80.f);
        float v = 0.f;
        for (int d = 0; d < DLAT; ++d) { float t = pooled[d] - m; v += t * t; }
        v *= (1.f / 80.f);
        float rstd = rsqrtf(v + 1e-5f);
        float r = 0.f;
        for (int d = 0; d < DLAT; ++d)
            r += ((pooled[d] - m) * rstd * g[d] + bt[d]) * wf[d];
        out[b] = r + bf[0];
    }
}

// ---------------- launcher ----------------
extern "C" void kernel_launch(void* const* d_in, const int* in_sizes, int n_in,
                              void* d_out, int out_size)
{
    const int*   spatial_pos = (const int*)d_in[0];
    const int*   edge_input  = (const int*)d_in[1];
    const int*   x_nodes     = (const int*)d_in[2];
    const int*   indeg       = (const int*)d_in[3];
    const int*   outdeg      = (const int*)d_in[4];
    const float* atom_emb    = (const float*)d_in[5];
    const float* indeg_emb   = (const float*)d_in[6];
    const float* outdeg_emb  = (const float*)d_in[7];
    const float* edge_emb    = (const float*)d_in[8];
    const float* edge_dis_w  = (const float*)d_in[9];
    const float* spatial_emb = (const float*)d_in[10];
    const float* ln1_g = (const float*)d_in[11];
    const float* ln1_b = (const float*)d_in[12];
    const float* Wq    = (const float*)d_in[13];
    const float* Wkv   = (const float*)d_in[14];
    const float* Wo    = (const float*)d_in[15];
    const float* bo    = (const float*)d_in[16];
    const float* ln2_g = (const float*)d_in[17];
    const float* ln2_b = (const float*)d_in[18];
    const float* W1    = (const float*)d_in[19];
    const float* b1    = (const float*)d_in[20];
    const float* W2    = (const float*)d_in[21];
    const float* b2    = (const float*)d_in[22];
    const float* lnf_g = (const float*)d_in[23];
    const float* lnf_b = (const float*)d_in[24];
    const float* Wf    = (const float*)d_in[25];
    const float* bf    = (const float*)d_in[26];
    float* out = (float*)d_out;

    float *bias_p, *x_p, *h_p, *q_p, *kv_p, *o_p, *ff_p;
    cudaGetSymbolAddress((void**)&bias_p, g_bias);
    cudaGetSymbolAddress((void**)&x_p, g_x);
    cudaGetSymbolAddress((void**)&h_p, g_h);
    cudaGetSymbolAddress((void**)&q_p, g_q);
    cudaGetSymbolAddress((void**)&kv_p, g_kv);
    cudaGetSymbolAddress((void**)&o_p, g_o);
    cudaGetSymbolAddress((void**)&ff_p, g_ff);

    cudaFuncSetAttribute(attn_mma_kernel, cudaFuncAttributeMaxDynamicSharedMemorySize, AT_SMEM_BYTES);

    bias_kernel<<<(BB * NN * NN) / 256, 256>>>(spatial_pos, edge_input, edge_emb, edge_dis_w,
                                               spatial_emb, bias_p);
    embed_kernel<<<(ROWS * DLAT + 255) / 256, 256>>>(x_nodes, indeg, outdeg,
                                                     atom_emb, indeg_emb, outdeg_emb, x_p);
    for (int l = 0; l < DEPTH; ++l) {
        ln_kernel<<<ROWS / 8, 256>>>(x_p, ln1_g + l * DLAT, ln1_b + l * DLAT, h_p);
        gemm_mma_kernel<128, 64><<<dim3(INNER / 64, ROWS / 128), 256>>>(
            h_p, Wq + (size_t)l * DLAT * INNER, nullptr, nullptr, q_p, ROWS, INNER, DLAT, 0);
        gemm_mma_kernel<128, 64><<<dim3(2 * INNER / 64, ROWS / 128), 256>>>(
            h_p, Wkv + (size_t)l * DLAT * 2 * INNER, nullptr, nullptr, kv_p, ROWS, 2 * INNER, DLAT, 0);
        attn_mma_kernel<<<BB * HEADS, 256, AT_SMEM_BYTES>>>(q_p, kv_p, bias_p, o_p);
        gemm_mma_kernel<64, 80><<<dim3(1, ROWS / 64), 256>>>(
            o_p, Wo + (size_t)l * INNER * DLAT, bo + l * DLAT, x_p, x_p, ROWS, DLAT, INNER, 5);
        ln_kernel<<<ROWS / 8, 256>>>(x_p, ln2_g + l * DLAT, ln2_b + l * DLAT, h_p);
        gemm_mma_kernel<64, 80><<<dim3(2, ROWS / 64), 256>>>(
            h_p, W1 + (size_t)l * DLAT * FFD, b1 + l * FFD, nullptr, ff_p, ROWS, FFD, DLAT, 3);
        gemm_mma_kernel<64, 80><<<dim3(1, ROWS / 64), 256>>>(
            ff_p, W2 + (size_t)l * FFD * DLAT, b2 + l * DLAT, x_p, x_p, ROWS, DLAT, FFD, 5);
    }
    head_kernel<<<BB, 128>>>(x_p, lnf_g, lnf_b, Wf, bf, out);
}

// round 10
// speedup vs baseline: 1.8653x; 1.1045x over previous
#include <cuda_runtime.h>
#include <cuda_bf16.h>
#include <math.h>
#include <stdint.h>

// ---------------- problem constants ----------------
#define BB 64
#define NN 128
#define DLAT 80
#define HEADS 8
#define DH 64
#define INNER 512
#define FFD 160
#define DEPTH 24
#define ROWS (BB * NN)          // 8192
#define MHD 20
#define QKVN 1536               // packed q|k|v columns

// ---------------- scratch (device globals) ----------------
__device__ float g_bias[BB * NN * NN];          // 4 MB
__device__ float g_x[ROWS * DLAT];
__device__ float g_h[ROWS * DLAT];              // tf32-rounded LN output
__device__ float g_qkv[ROWS * QKVN];            // tf32-rounded
__device__ float g_o[ROWS * INNER];             // tf32-rounded
__device__ float g_ff[ROWS * FFD];              // tf32-rounded
// pre-rounded / packed weights
__device__ float g_wqkv[DEPTH * DLAT * QKVN];
__device__ float g_wo[DEPTH * INNER * DLAT];
__device__ float g_w1[DEPTH * DLAT * FFD];
__device__ float g_w2[DEPTH * FFD * DLAT];

// ---------------- tf32 helpers ----------------
__device__ __forceinline__ uint32_t f2tf(float x) {
    uint32_t r;
    asm("cvt.rna.tf32.f32 %0, %1;" : "=r"(r) : "f"(x));
    return r;
}
__device__ __forceinline__ float roundtf(float x) { return __uint_as_float(f2tf(x)); }

__device__ __forceinline__ void mma_tf32(float* c, const uint32_t* a, uint32_t b0, uint32_t b1) {
    asm("mma.sync.aligned.m16n8k8.row.col.f32.tf32.tf32.f32 "
        "{%0,%1,%2,%3},{%4,%5,%6,%7},{%8,%9},{%0,%1,%2,%3};"
        : "+f"(c[0]), "+f"(c[1]), "+f"(c[2]), "+f"(c[3])
        : "r"(a[0]), "r"(a[1]), "r"(a[2]), "r"(a[3]), "r"(b0), "r"(b1));
}

// ---------------- weight pack kernels (run once per launch) ----------------
__global__ __launch_bounds__(256) void pack_qkv_kernel(
    const float* __restrict__ Wq, const float* __restrict__ Wkv, float* __restrict__ out)
{
    int idx = blockIdx.x * blockDim.x + threadIdx.x;
    if (idx >= DEPTH * DLAT * QKVN) return;
    int lk = idx / QKVN;        // l*80 + k
    int c = idx - lk * QKVN;
    float v = (c < INNER) ? Wq[(size_t)lk * INNER + c]
                          : Wkv[(size_t)lk * (2 * INNER) + (c - INNER)];
    out[idx] = roundtf(v);
}

__global__ __launch_bounds__(256) void round_copy_kernel(
    const float* __restrict__ in, float* __restrict__ out, int n)
{
    int i = blockIdx.x * blockDim.x + threadIdx.x;
    if (i < n) out[i] = roundtf(in[i]);
}

// ---------------- bias precompute ----------------
__global__ __launch_bounds__(256) void bias_kernel(
    const int* __restrict__ sp, const int* __restrict__ ei,
    const float* __restrict__ eemb, const float* __restrict__ edw,
    const float* __restrict__ semb, float* __restrict__ bias)
{
    __shared__ float s_eemb[64];
    __shared__ float s_edw[MHD];
    __shared__ float s_semb[40];
    int tid = threadIdx.x;
    if (tid < 64) s_eemb[tid] = eemb[tid];
    if (tid < MHD) s_edw[tid] = edw[tid];
    if (tid < 40) s_semb[tid] = semb[tid];
    __syncthreads();
    int g = blockIdx.x * blockDim.x + tid;
    if (g >= BB * NN * NN) return;
    const int* ep = ei + (size_t)g * (MHD * 3);
    float acc = 0.f;
#pragma unroll
    for (int hh = 0; hh < MHD; ++hh) {
        float m = (s_eemb[ep[hh * 3]] + s_eemb[ep[hh * 3 + 1]] + s_eemb[ep[hh * 3 + 2]]) * (1.f / 3.f);
        acc += m * s_edw[hh];
    }
    int p = sp[g];
    int spv = (p == 0) ? 1 : p;
    if (spv > 1) spv -= 1;
    if (spv > MHD) spv = MHD;
    bias[g] = acc / (float)spv + s_semb[p];
}

// ---------------- node embedding ----------------
__global__ __launch_bounds__(256) void embed_kernel(
    const int* __restrict__ xn, const int* __restrict__ ind, const int* __restrict__ outd,
    const float* __restrict__ ae, const float* __restrict__ ie, const float* __restrict__ oe,
    float* __restrict__ x)
{
    int i = blockIdx.x * blockDim.x + threadIdx.x;
    if (i >= ROWS * DLAT) return;
    int row = i / DLAT, d = i - row * DLAT;
    x[i] = ae[xn[row] * DLAT + d] + ie[ind[row] * DLAT + d] + oe[outd[row] * DLAT + d];
}

// ---------------- LayerNorm (warp per row, D=80), tf32-rounded output -------
__global__ __launch_bounds__(256) void ln_kernel(
    const float* __restrict__ x, const float* __restrict__ g,
    const float* __restrict__ bt, float* __restrict__ y)
{
    int gw = (blockIdx.x * blockDim.x + threadIdx.x) >> 5;
    int lane = threadIdx.x & 31;
    if (gw >= ROWS) return;
    const float* xr = x + (size_t)gw * DLAT;
    float v0 = xr[lane];
    float v1 = xr[lane + 32];
    float v2 = (lane < 16) ? xr[lane + 64] : 0.f;
    float s = v0 + v1 + v2;
#pragma unroll
    for (int off = 16; off > 0; off >>= 1) s += __shfl_xor_sync(0xffffffffu, s, off);
    float mean = s * (1.f / 80.f);
    float d0 = v0 - mean, d1 = v1 - mean, d2 = (lane < 16) ? (v2 - mean) : 0.f;
    float sq = d0 * d0 + d1 * d1 + d2 * d2;
#pragma unroll
    for (int off = 16; off > 0; off >>= 1) sq += __shfl_xor_sync(0xffffffffu, sq, off);
    float rstd = rsqrtf(sq * (1.f / 80.f) + 1e-5f);
    float* yr = y + (size_t)gw * DLAT;
    yr[lane] = roundtf(d0 * rstd * g[lane] + bt[lane]);
    yr[lane + 32] = roundtf(d1 * rstd * g[lane + 32] + bt[lane + 32]);
    if (lane < 16) yr[lane + 64] = roundtf(d2 * rstd * g[lane + 64] + bt[lane + 64]);
}

// ---------------- tf32 tensor-core GEMM (pre-rounded inputs) ----------------
// C[M,N] = A[M,K] @ W[K,N]; M%BM==0, N%BN==0, K%BK==0 (no guards).
// flags: 1 = +bias(col), 2 = exact GELU, 4 = +residual, 8 = round output to tf32
template<int BM, int BN, int BK>
__global__ __launch_bounds__(256) void gemm_mma_kernel(
    const float* __restrict__ A, const float* __restrict__ W,
    const float* __restrict__ bi, const float* __restrict__ res,
    float* __restrict__ C, int M, int N, int K, int flags)
{
    constexpr int MI = BM / 64;       // m16 tiles per warp (warpM covers 16*MI rows)
    constexpr int NI = BN / 16;       // n8 tiles per warp
    constexpr int AP = BK + 4;        // A smem pitch
    constexpr int BP = BN + 8;        // B smem pitch
    __shared__ uint32_t As[BM * AP];
    __shared__ uint32_t Bs[BK * BP];
    int tid = threadIdx.x;
    int wid = tid >> 5, lane = tid & 31;
    int warpM = wid >> 1, warpN = wid & 1;
    int m0 = blockIdx.y * BM, n0 = blockIdx.x * BN;
    int lq = lane >> 2, lr = lane & 3;

    float c[MI][NI][4];
#pragma unroll
    for (int mi = 0; mi < MI; ++mi)
#pragma unroll
        for (int ni = 0; ni < NI; ++ni)
#pragma unroll
            for (int t = 0; t < 4; ++t) c[mi][ni][t] = 0.f;

    for (int k0 = 0; k0 < K; k0 += BK) {
        __syncthreads();
        // A tile: BM x BK (pure bit copy, already tf32-rounded)
#pragma unroll
        for (int idx = tid; idx < BM * (BK / 4); idx += 256) {
            int r = idx / (BK / 4), c4 = (idx % (BK / 4)) * 4;
            uint4 v = *(const uint4*)(A + (size_t)(m0 + r) * K + k0 + c4);
            *(uint4*)&As[r * AP + c4] = v;
        }
        // B tile: BK x BN
#pragma unroll
        for (int idx = tid; idx < BK * (BN / 4); idx += 256) {
            int r = idx / (BN / 4), c4 = (idx % (BN / 4)) * 4;
            uint4 v = *(const uint4*)(W + (size_t)(k0 + r) * N + n0 + c4);
            *(uint4*)&Bs[r * BP + c4] = v;
        }
        __syncthreads();
#pragma unroll
        for (int kk = 0; kk < BK; kk += 8) {
            uint32_t a[MI][4];
#pragma unroll
            for (int mi = 0; mi < MI; ++mi) {
                int row = warpM * (16 * MI) + mi * 16 + lq;
                a[mi][0] = As[row * AP + kk + lr];
                a[mi][1] = As[(row + 8) * AP + kk + lr];
                a[mi][2] = As[row * AP + kk + lr + 4];
                a[mi][3] = As[(row + 8) * AP + kk + lr + 4];
            }
#pragma unroll
            for (int ni = 0; ni < NI; ++ni) {
                int col = warpN * (8 * NI) + ni * 8 + lq;
                uint32_t b0 = Bs[(kk + lr) * BP + col];
                uint32_t b1 = Bs[(kk + lr + 4) * BP + col];
#pragma unroll
                for (int mi = 0; mi < MI; ++mi) mma_tf32(c[mi][ni], a[mi], b0, b1);
            }
        }
    }
    // epilogue (N multiple of BN: no col guards)
#pragma unroll
    for (int mi = 0; mi < MI; ++mi) {
        int r = m0 + warpM * (16 * MI) + mi * 16 + lq;
#pragma unroll
        for (int ni = 0; ni < NI; ++ni) {
            int cc = n0 + warpN * (8 * NI) + ni * 8 + 2 * lr;
#pragma unroll
            for (int half = 0; half < 2; ++half) {
                int row = r + half * 8;
                float v0 = c[mi][ni][half * 2 + 0];
                float v1 = c[mi][ni][half * 2 + 1];
                if (flags & 1) { v0 += bi[cc]; v1 += bi[cc + 1]; }
                if (flags & 2) {
                    v0 = 0.5f * v0 * (1.0f + erff(v0 * 0.70710678118f));
                    v1 = 0.5f * v1 * (1.0f + erff(v1 * 0.70710678118f));
                }
                if (flags & 4) {
                    float2 rv = *(const float2*)(res + (size_t)row * N + cc);
                    v0 += rv.x; v1 += rv.y;
                }
                if (flags & 8) { v0 = roundtf(v0); v1 = roundtf(v1); }
                float2 ov; ov.x = v0; ov.y = v1;
                *(float2*)(C + (size_t)row * N + cc) = ov;
            }
        }
    }
}

// ---------------- fused tensor-core attention per (b, head) ----------------
// qkv rows have pitch 1536: [0:512)=Q, [512:1024)=K, [1024:1536)=V (tf32-rounded)
#define AT_KPITCH 68
#define AT_PPITCH 132
#define AT_SMEM_WORDS (128 * AT_KPITCH * 2 + 8 * 16 * AT_PPITCH)
#define AT_SMEM_BYTES (AT_SMEM_WORDS * 4)
__global__ __launch_bounds__(256) void attn_mma_kernel(
    const float* __restrict__ qkv, const float* __restrict__ bias, float* __restrict__ o)
{
    extern __shared__ uint32_t sm[];
    uint32_t* Ks = sm;
    uint32_t* Vs = sm + 128 * AT_KPITCH;
    uint32_t* QP = sm + 2 * 128 * AT_KPITCH;

    int bh = blockIdx.x;
    int b = bh >> 3, hh = bh & 7;
    const float* base = qkv + (size_t)b * NN * QKVN;
    const float* qp = base + hh * DH;
    const float* kp = base + INNER + hh * DH;
    const float* vp = base + 2 * INNER + hh * DH;
    int tid = threadIdx.x;

    // load Q, K, V tiles (pure bit copies)
#pragma unroll
    for (int idx = tid; idx < 128 * 16; idx += 256) {
        int r = idx >> 4, c4 = (idx & 15) * 4;
        uint4 qv = *(const uint4*)(qp + (size_t)r * QKVN + c4);
        uint4 kvv = *(const uint4*)(kp + (size_t)r * QKVN + c4);
        uint4 vv = *(const uint4*)(vp + (size_t)r * QKVN + c4);
        *(uint4*)&QP[r * AT_KPITCH + c4] = qv;
        *(uint4*)&Ks[r * AT_KPITCH + c4] = kvv;
        *(uint4*)&Vs[r * AT_KPITCH + c4] = vv;
    }
    __syncthreads();

    int w = tid >> 5, lane = tid & 31;
    int lq = lane >> 2, lr = lane & 3;
    int i0 = w * 16;

    // phase 1: S = Q K^T
    float s[16][4];
#pragma unroll
    for (int ni = 0; ni < 16; ++ni)
#pragma unroll
        for (int t = 0; t < 4; ++t) s[ni][t] = 0.f;

#pragma unroll
    for (int kt = 0; kt < 8; ++kt) {
        uint32_t a[4];
        int row = i0 + lq;
        a[0] = QP[row * AT_KPITCH + kt * 8 + lr];
        a[1] = QP[(row + 8) * AT_KPITCH + kt * 8 + lr];
        a[2] = QP[row * AT_KPITCH + kt * 8 + lr + 4];
        a[3] = QP[(row + 8) * AT_KPITCH + kt * 8 + lr + 4];
#pragma unroll
        for (int ni = 0; ni < 16; ++ni) {
            uint32_t b0 = Ks[(ni * 8 + lq) * AT_KPITCH + kt * 8 + lr];
            uint32_t b1 = Ks[(ni * 8 + lq) * AT_KPITCH + kt * 8 + lr + 4];
            mma_tf32(s[ni], a, b0, b1);
        }
    }

    // scale + bias + softmax
    const float* bb = bias + (size_t)b * NN * NN;
    int r0 = i0 + lq;
#pragma unroll
    for (int ni = 0; ni < 16; ++ni) {
        int cc = ni * 8 + 2 * lr;
        float2 b0v = __ldg((const float2*)(bb + (size_t)r0 * NN + cc));
        float2 b1v = __ldg((const float2*)(bb + (size_t)(r0 + 8) * NN + cc));
        s[ni][0] = s[ni][0] * 0.125f + b0v.x;
        s[ni][1] = s[ni][1] * 0.125f + b0v.y;
        s[ni][2] = s[ni][2] * 0.125f + b1v.x;
        s[ni][3] = s[ni][3] * 0.125f + b1v.y;
    }
    float mA = -1e30f, mB = -1e30f;
#pragma unroll
    for (int ni = 0; ni < 16; ++ni) {
        mA = fmaxf(mA, fmaxf(s[ni][0], s[ni][1]));
        mB = fmaxf(mB, fmaxf(s[ni][2], s[ni][3]));
    }
    mA = fmaxf(mA, __shfl_xor_sync(0xffffffffu, mA, 1));
    mA = fmaxf(mA, __shfl_xor_sync(0xffffffffu, mA, 2));
    mB = fmaxf(mB, __shfl_xor_sync(0xffffffffu, mB, 1));
    mB = fmaxf(mB, __shfl_xor_sync(0xffffffffu, mB, 2));
    float sA = 0.f, sB = 0.f;
#pragma unroll
    for (int ni = 0; ni < 16; ++ni) {
        s[ni][0] = __expf(s[ni][0] - mA);
        s[ni][1] = __expf(s[ni][1] - mA);
        s[ni][2] = __expf(s[ni][2] - mB);
        s[ni][3] = __expf(s[ni][3] - mB);
        sA += s[ni][0] + s[ni][1];
        sB += s[ni][2] + s[ni][3];
    }
    sA += __shfl_xor_sync(0xffffffffu, sA, 1);
    sA += __shfl_xor_sync(0xffffffffu, sA, 2);
    sB += __shfl_xor_sync(0xffffffffu, sB, 1);
    sB += __shfl_xor_sync(0xffffffffu, sB, 2);

    __syncthreads();   // Q reads done before P overwrites union region
    uint32_t* Pw = QP + w * 16 * AT_PPITCH;
#pragma unroll
    for (int ni = 0; ni < 16; ++ni) {
        int cc = ni * 8 + 2 * lr;
        Pw[lq * AT_PPITCH + cc] = f2tf(s[ni][0]);
        Pw[lq * AT_PPITCH + cc + 1] = f2tf(s[ni][1]);
        Pw[(lq + 8) * AT_PPITCH + cc] = f2tf(s[ni][2]);
        Pw[(lq + 8) * AT_PPITCH + cc + 1] = f2tf(s[ni][3]);
    }
    __syncwarp();

    // phase 2: O = P V
    float oc[8][4];
#pragma unroll
    for (int ni = 0; ni < 8; ++ni)
#pragma unroll
        for (int t = 0; t < 4; ++t) oc[ni][t] = 0.f;
#pragma unroll
    for (int kt = 0; kt < 16; ++kt) {
        uint32_t a[4];
        a[0] = Pw[lq * AT_PPITCH + kt * 8 + lr];
        a[1] = Pw[(lq + 8) * AT_PPITCH + kt * 8 + lr];
        a[2] = Pw[lq * AT_PPITCH + kt * 8 + lr + 4];
        a[3] = Pw[(lq + 8) * AT_PPITCH + kt * 8 + lr + 4];
#pragma unroll
        for (int ni = 0; ni < 8; ++ni) {
            uint32_t b0 = Vs[(kt * 8 + lr) * AT_KPITCH + ni * 8 + lq];
            uint32_t b1 = Vs[(kt * 8 + lr + 4) * AT_KPITCH + ni * 8 + lq];
            mma_tf32(oc[ni], a, b0, b1);
        }
    }
    // normalize + store (rounded: consumed by O-proj GEMM)
    float invA = 1.f / sA, invB = 1.f / sB;
    float* op = o + (size_t)b * NN * INNER + hh * DH;
#pragma unroll
    for (int ni = 0; ni < 8; ++ni) {
        int cc = ni * 8 + 2 * lr;
        float2 v0; v0.x = roundtf(oc[ni][0] * invA); v0.y = roundtf(oc[ni][1] * invA);
        float2 v1; v1.x = roundtf(oc[ni][2] * invB); v1.y = roundtf(oc[ni][3] * invB);
        *(float2*)(op + (size_t)r0 * INNER + cc) = v0;
        *(float2*)(op + (size_t)(r0 + 8) * INNER + cc) = v1;
    }
}

// ---------------- final head ----------------
__global__ __launch_bounds__(128) void head_kernel(
    const float* __restrict__ x, const float* __restrict__ g, const float* __restrict__ bt,
    const float* __restrict__ wf, const float* __restrict__ bf, float* __restrict__ out)
{
    int b = blockIdx.x;
    __shared__ float pooled[DLAT];
    int tid = threadIdx.x;
    if (tid < DLAT) {
        float s = 0.f;
        for (int n = 0; n < NN; ++n) s += x[((size_t)b * NN + n) * DLAT + tid];
        pooled[tid] = s * (1.f / 128.f);
    }
    __syncthreads();
    if (tid == 0) {
        float m = 0.f;
        for (int d = 0; d < DLAT; ++d) m += pooled[d];
        m *= (1.f / 80.f);
        float v = 0.f;
        for (int d = 0; d < DLAT; ++d) { float t = pooled[d] - m; v += t * t; }
        v *= (1.f / 80.f);
        float rstd = rsqrtf(v + 1e-5f);
        float r = 0.f;
        for (int d = 0; d < DLAT; ++d)
            r += ((pooled[d] - m) * rstd * g[d] + bt[d]) * wf[d];
        out[b] = r + bf[0];
    }
}

// ---------------- launcher ----------------
extern "C" void kernel_launch(void* const* d_in, const int* in_sizes, int n_in,
                              void* d_out, int out_size)
{
    const int*   spatial_pos = (const int*)d_in[0];
    const int*   edge_input  = (const int*)d_in[1];
    const int*   x_nodes     = (const int*)d_in[2];
    const int*   indeg       = (const int*)d_in[3];
    const int*   outdeg      = (const int*)d_in[4];
    const float* atom_emb    = (const float*)d_in[5];
    const float* indeg_emb   = (const float*)d_in[6];
    const float* outdeg_emb  = (const float*)d_in[7];
    const float* edge_emb    = (const float*)d_in[8];
    const float* edge_dis_w  = (const float*)d_in[9];
    const float* spatial_emb = (const float*)d_in[10];
    const float* ln1_g = (const float*)d_in[11];
    const float* ln1_b = (const float*)d_in[12];
    const float* Wq    = (const float*)d_in[13];
    const float* Wkv   = (const float*)d_in[14];
    const float* Wo    = (const float*)d_in[15];
    const float* bo    = (const float*)d_in[16];
    const float* ln2_g = (const float*)d_in[17];
    const float* ln2_b = (const float*)d_in[18];
    const float* W1    = (const float*)d_in[19];
    const float* b1    = (const float*)d_in[20];
    const float* W2    = (const float*)d_in[21];
    const float* b2    = (const float*)d_in[22];
    const float* lnf_g = (const float*)d_in[23];
    const float* lnf_b = (const float*)d_in[24];
    const float* Wf    = (const float*)d_in[25];
    const float* bf    = (const float*)d_in[26];
    float* out = (float*)d_out;

    float *bias_p, *x_p, *h_p, *qkv_p, *o_p, *ff_p;
    float *wqkv_p, *wo_p, *w1_p, *w2_p;
    cudaGetSymbolAddress((void**)&bias_p, g_bias);
    cudaGetSymbolAddress((void**)&x_p, g_x);
    cudaGetSymbolAddress((void**)&h_p, g_h);
    cudaGetSymbolAddress((void**)&qkv_p, g_qkv);
    cudaGetSymbolAddress((void**)&o_p, g_o);
    cudaGetSymbolAddress((void**)&ff_p, g_ff);
    cudaGetSymbolAddress((void**)&wqkv_p, g_wqkv);
    cudaGetSymbolAddress((void**)&wo_p, g_wo);
    cudaGetSymbolAddress((void**)&w1_p, g_w1);
    cudaGetSymbolAddress((void**)&w2_p, g_w2);

    cudaFuncSetAttribute(attn_mma_kernel, cudaFuncAttributeMaxDynamicSharedMemorySize, AT_SMEM_BYTES);

    // one-time packs (rounded weights)
    pack_qkv_kernel<<<(DEPTH * DLAT * QKVN + 255) / 256, 256>>>(Wq, Wkv, wqkv_p);
    round_copy_kernel<<<(DEPTH * INNER * DLAT + 255) / 256, 256>>>(Wo, wo_p, DEPTH * INNER * DLAT);
    round_copy_kernel<<<(DEPTH * DLAT * FFD + 255) / 256, 256>>>(W1, w1_p, DEPTH * DLAT * FFD);
    round_copy_kernel<<<(DEPTH * FFD * DLAT + 255) / 256, 256>>>(W2, w2_p, DEPTH * FFD * DLAT);

    bias_kernel<<<(BB * NN * NN) / 256, 256>>>(spatial_pos, edge_input, edge_emb, edge_dis_w,
                                               spatial_emb, bias_p);
    embed_kernel<<<(ROWS * DLAT + 255) / 256, 256>>>(x_nodes, indeg, outdeg,
                                                     atom_emb, indeg_emb, outdeg_emb, x_p);
    for (int l = 0; l < DEPTH; ++l) {
        ln_kernel<<<ROWS / 8, 256>>>(x_p, ln1_g + l * DLAT, ln1_b + l * DLAT, h_p);
        // fused QKV projection: [8192,80] @ [80,1536]
        gemm_mma_kernel<128, 64, 40><<<dim3(QKVN / 64, ROWS / 128), 256>>>(
            h_p, wqkv_p + (size_t)l * DLAT * QKVN, nullptr, nullptr, qkv_p,
            ROWS, QKVN, DLAT, 8);
        attn_mma_kernel<<<BB * HEADS, 256, AT_SMEM_BYTES>>>(qkv_p, bias_p, o_p);
        gemm_mma_kernel<64, 80, 32><<<dim3(1, ROWS / 64), 256>>>(
            o_p, wo_p + (size_t)l * INNER * DLAT, bo + l * DLAT, x_p, x_p,
            ROWS, DLAT, INNER, 5);
        ln_kernel<<<ROWS / 8, 256>>>(x_p, ln2_g + l * DLAT, ln2_b + l * DLAT, h_p);
        gemm_mma_kernel<64, 80, 40><<<dim3(2, ROWS / 64), 256>>>(
            h_p, w1_p + (size_t)l * DLAT * FFD, b1 + l * FFD, nullptr, ff_p,
            ROWS, FFD, DLAT, 11);
        gemm_mma_kernel<64, 80, 32><<<dim3(1, ROWS / 64), 256>>>(
            ff_p, w2_p + (size_t)l * FFD * DLAT, b2 + l * DLAT, x_p, x_p,
            ROWS, DLAT, FFD, 5);
    }
    head_kernel<<<BB, 128>>>(x_p, lnf_g, lnf_b, Wf, bf, out);
}